// round 4
// baseline (speedup 1.0000x reference)
#include <cuda_runtime.h>
#include <cuda_bf16.h>

#define BSZ 64
#define NC  32

// Spatial sizes: 255 -> 127 -> 63 -> 31 -> 15 -> 7 (stride 2, VALID, k=3)
static const int H0 = 255, H1 = 127, H2 = 63, H3 = 31, H4 = 15, H5 = 7;

// ---------------- scratch ----------------
__device__ float g_bufA[BSZ * NC * 127 * 127];
__device__ float g_bufB[BSZ * NC * 63 * 63];
__device__ float g_feat[BSZ * NC * 7 * 7];
__device__ float g_fc1[BSZ * 20];
__device__ float g_coef[BSZ * 27];

// ---------------- unified conv: ICN -> 32, stride 2, fused bias+relu+bn ----------------
// PX output pixels x OCG output channels per thread. blockIdx.y = channel group.
// Register budget: PX*OCG acc + (2*PX+1) inputs. Keep <= ~64.
template <int HIN, int HOUT, int ICN, int OCG, int PX>
__global__ void __launch_bounds__(128) conv_kernel(
    const float* __restrict__ x, const float* __restrict__ w,
    const float* __restrict__ cbias,
    const float* __restrict__ bng, const float* __restrict__ bnb,
    const float* __restrict__ bnm, const float* __restrict__ bnv,
    float* __restrict__ out)
{
    constexpr int NXP = (HOUT + PX - 1) / PX;
    constexpr int NIN = 2 * PX + 1;
    __shared__ float ws[OCG * ICN * 9];
    __shared__ float sc_s[OCG], sh_s[OCG], bias_s[OCG];

    const int g   = blockIdx.y;
    const int oc0 = g * OCG;

    for (int i = threadIdx.x; i < OCG * ICN * 9; i += blockDim.x)
        ws[i] = w[oc0 * ICN * 9 + i];
    if (threadIdx.x < OCG) {
        int oc = oc0 + threadIdx.x;
        float sc = bng[oc] * rsqrtf(bnv[oc] + 1e-5f);
        sc_s[threadIdx.x]   = sc;
        sh_s[threadIdx.x]   = bnb[oc] - bnm[oc] * sc;
        bias_s[threadIdx.x] = cbias[oc];
    }
    __syncthreads();

    int idx = blockIdx.x * blockDim.x + threadIdx.x;
    int total = BSZ * HOUT * NXP;
    if (idx >= total) return;
    int xp = idx % NXP;
    int t  = idx / NXP;
    int oy = t % HOUT;
    int b  = t / HOUT;
    int ox0 = PX * xp;
    bool full = (ox0 + PX - 1) < HOUT;   // then 2*ox0 + 2*PX <= HIN-1 (HIN = 2*HOUT+1)

    float acc[PX][OCG];
#pragma unroll
    for (int j = 0; j < PX; ++j)
#pragma unroll
        for (int oc = 0; oc < OCG; ++oc) acc[j][oc] = 0.f;

    const float* xb = x + ((size_t)(b * ICN) * HIN + 2 * oy) * HIN + 2 * ox0;

    for (int ic = 0; ic < ICN; ++ic) {
        const float* xc = xb + (size_t)ic * HIN * HIN;
#pragma unroll
        for (int ky = 0; ky < 3; ++ky) {
            const float* row = xc + ky * HIN;
            float xin[NIN];
            if (full) {
#pragma unroll
                for (int i = 0; i < NIN; ++i) xin[i] = row[i];
            } else {
#pragma unroll
                for (int i = 0; i < NIN; ++i)
                    xin[i] = (2 * ox0 + i < HIN) ? row[i] : 0.f;
            }
#pragma unroll
            for (int kx = 0; kx < 3; ++kx) {
                const float* wp = ws + ic * 9 + ky * 3 + kx;
#pragma unroll
                for (int oc = 0; oc < OCG; ++oc) {
                    float wv = wp[oc * ICN * 9];
#pragma unroll
                    for (int j = 0; j < PX; ++j)
                        acc[j][oc] = fmaf(xin[2 * j + kx], wv, acc[j][oc]);
                }
            }
        }
    }

    size_t obase = ((size_t)(b * NC + oc0) * HOUT + oy) * HOUT + ox0;
#pragma unroll
    for (int oc = 0; oc < OCG; ++oc) {
#pragma unroll
        for (int j = 0; j < PX; ++j) {
            if (full || (ox0 + j) < HOUT) {
                float y = fmaxf(acc[j][oc] + bias_s[oc], 0.f) * sc_s[oc] + sh_s[oc];
                out[obase + (size_t)oc * HOUT * HOUT + j] = y;
            }
        }
    }
}

// ---------------- FC1: [64,1568] @ [1568,20]^T + b, relu ----------------
__global__ void fc1_kernel(const float* __restrict__ feat, const float* __restrict__ w,
                           const float* __restrict__ bias, float* __restrict__ out)
{
    int gw   = (blockIdx.x * blockDim.x + threadIdx.x) >> 5;
    int lane = threadIdx.x & 31;
    if (gw >= BSZ * 20) return;
    int j = gw % 20, b = gw / 20;
    const float* f  = feat + b * 1568;
    const float* wr = w + j * 1568;
    float s = 0.f;
    for (int k = lane; k < 1568; k += 32) s = fmaf(f[k], wr[k], s);
#pragma unroll
    for (int o = 16; o; o >>= 1) s += __shfl_xor_sync(0xffffffffu, s, o);
    if (lane == 0) out[b * 20 + j] = fmaxf(s + bias[j], 0.f);
}

// ---------------- FC2 + cubic-spline solve (Thomas) ----------------
__global__ void spline_kernel(const float* __restrict__ fc1,
                              const float* __restrict__ l2w, const float* __restrict__ l2b,
                              float* __restrict__ coef)
{
    int b = blockIdx.x * blockDim.x + threadIdx.x;
    if (b >= BSZ) return;

    float ys[10];
#pragma unroll
    for (int k = 0; k < 10; ++k) {
        float s = l2b[k];
#pragma unroll
        for (int j = 0; j < 20; ++j) s = fmaf(fc1[b * 20 + j], l2w[k * 20 + j], s);
        ys[k] = s;
    }

    const float h = (float)(1.0 / 9.0);
    const float c6h2 = 6.0f * 81.0f;
    float d[8];
#pragma unroll
    for (int i = 0; i < 8; ++i) d[i] = c6h2 * (ys[i] - 2.f * ys[i + 1] + ys[i + 2]);

    float cp[8], dp[8];
    cp[0] = 0.25f; dp[0] = d[0] * 0.25f;
#pragma unroll
    for (int i = 1; i < 8; ++i) {
        float mden = 4.f - cp[i - 1];
        cp[i] = 1.f / mden;
        dp[i] = (d[i] - dp[i - 1]) / mden;
    }
    float M[10];
    M[0] = 0.f; M[9] = 0.f;
    M[8] = dp[7];
#pragma unroll
    for (int i = 6; i >= 0; --i) M[i + 1] = dp[i] - cp[i] * M[i + 2];

#pragma unroll
    for (int i = 0; i < 9; ++i) {
        coef[b * 27 + i]      = (M[i + 1] - M[i]) / (6.f * h);
        coef[b * 27 + 9 + i]  = M[i] * 0.5f;
        coef[b * 27 + 18 + i] = (ys[i + 1] - ys[i]) / h - (M[i + 1] + 2.f * M[i]) * (h / 6.f);
    }
}

// ---------------- final fused bucketize + gather + cubic eval (float4) ----------------
__global__ void eval_kernel(const float4* __restrict__ x, const float* __restrict__ coef,
                            float4* __restrict__ out, int n4)
{
    int idx = blockIdx.x * blockDim.x + threadIdx.x;
    if (idx >= n4) return;
    const int per = 3 * 255 * 255;
    int i0 = idx * 4;
    int b0 = i0 / per;
    int r0 = i0 - b0 * per;

    float4 xv = x[idx];
    float vals[4] = {xv.x, xv.y, xv.z, xv.w};
    float res[4];
    const float h = (float)(1.0 / 9.0);
#pragma unroll
    for (int j = 0; j < 4; ++j) {
        int b = b0 + ((r0 + j) >= per ? 1 : 0);
        float v = vals[j];
        float q = fminf(fmaxf(v / h, 0.f), 8.f);
        int xi = (int)floorf(q);
        float xf = v - (float)xi * h;
        const float* cf = coef + b * 27;
        float a  = __ldg(cf + xi);
        float bb = __ldg(cf + 9 + xi);
        float cc = __ldg(cf + 18 + xi);
        res[j] = ((a * xf + bb) * xf + cc) * xf;
    }
    out[idx] = make_float4(res[0], res[1], res[2], res[3]);
}

// ---------------- launch ----------------
extern "C" void kernel_launch(void* const* d_in, const int* in_sizes, int n_in,
                              void* d_out, int out_size)
{
    const float* batch = (const float*)d_in[0];
    const float* c1_w  = (const float*)d_in[1];
    const float* c1_b  = (const float*)d_in[2];
    const float* cw    = (const float*)d_in[3];
    const float* cb    = (const float*)d_in[4];
    const float* bn_g  = (const float*)d_in[5];
    const float* bn_b  = (const float*)d_in[6];
    const float* bn_m  = (const float*)d_in[7];
    const float* bn_v  = (const float*)d_in[8];
    const float* l1_w  = (const float*)d_in[9];
    const float* l1_b  = (const float*)d_in[10];
    const float* l2_w  = (const float*)d_in[11];
    const float* l2_b  = (const float*)d_in[12];
    float* out = (float*)d_out;

    float* bufA; cudaGetSymbolAddress((void**)&bufA, g_bufA);
    float* bufB; cudaGetSymbolAddress((void**)&bufB, g_bufB);
    float* feat; cudaGetSymbolAddress((void**)&feat, g_feat);
    float* fc1;  cudaGetSymbolAddress((void**)&fc1,  g_fc1);
    float* coef; cudaGetSymbolAddress((void**)&coef, g_coef);

    const int TB = 128;

    // conv1: 3 -> 32, 255 -> 127.  PX=4, OCG=8 (32 acc regs). 2032 x 4 blocks.
    {
        constexpr int NXP = (H1 + 3) / 4;
        int total = BSZ * H1 * NXP;
        dim3 grid((total + TB - 1) / TB, NC / 8);
        conv_kernel<H0, H1, 3, 8, 4><<<grid, TB>>>(
            batch, c1_w, c1_b, bn_g, bn_b, bn_m, bn_v, bufA);
    }
    // conv2: 127 -> 63.  PX=4, OCG=8. 504 x 4 blocks.
    {
        constexpr int NXP = (H2 + 3) / 4;
        int total = BSZ * H2 * NXP;
        dim3 grid((total + TB - 1) / TB, NC / 8);
        conv_kernel<H1, H2, NC, 8, 4><<<grid, TB>>>(
            bufA, cw + 0 * NC * NC * 9, cb + 0 * NC,
            bn_g + 1 * NC, bn_b + 1 * NC, bn_m + 1 * NC, bn_v + 1 * NC, bufB);
    }
    // conv3: 63 -> 31.  PX=4, OCG=8. 124 x 4 blocks.
    {
        constexpr int NXP = (H3 + 3) / 4;
        int total = BSZ * H3 * NXP;
        dim3 grid((total + TB - 1) / TB, NC / 8);
        conv_kernel<H2, H3, NC, 8, 4><<<grid, TB>>>(
            bufB, cw + 1 * NC * NC * 9, cb + 1 * NC,
            bn_g + 2 * NC, bn_b + 2 * NC, bn_m + 2 * NC, bn_v + 2 * NC, bufA);
    }
    // conv4: 31 -> 15.  PX=2, OCG=4. 60 x 8 = 480 blocks (parallelism over ratio).
    {
        constexpr int NXP = (H4 + 1) / 2;
        int total = BSZ * H4 * NXP;
        dim3 grid((total + TB - 1) / TB, NC / 4);
        conv_kernel<H3, H4, NC, 4, 2><<<grid, TB>>>(
            bufA, cw + 2 * NC * NC * 9, cb + 2 * NC,
            bn_g + 3 * NC, bn_b + 3 * NC, bn_m + 3 * NC, bn_v + 3 * NC, bufB);
    }
    // conv5: 15 -> 7.  PX=2, OCG=2. 14 x 16 = 224 blocks.
    {
        constexpr int NXP = (H5 + 1) / 2;
        int total = BSZ * H5 * NXP;
        dim3 grid((total + TB - 1) / TB, NC / 2);
        conv_kernel<H4, H5, NC, 2, 2><<<grid, TB>>>(
            bufB, cw + 3 * NC * NC * 9, cb + 3 * NC,
            bn_g + 4 * NC, bn_b + 4 * NC, bn_m + 4 * NC, bn_v + 4 * NC, feat);
    }
    // FC1
    {
        int warps = BSZ * 20;
        int threads = warps * 32;
        fc1_kernel<<<(threads + 255) / 256, 256>>>(feat, l1_w, l1_b, fc1);
    }
    // FC2 + spline solve
    spline_kernel<<<1, BSZ>>>(fc1, l2_w, l2_b, coef);

    // Final fused eval
    {
        int n4 = out_size / 4;
        eval_kernel<<<(n4 + 255) / 256, 256>>>((const float4*)batch, coef, (float4*)out, n4);
    }
}

// round 5
// speedup vs baseline: 2.4984x; 2.4984x over previous
#include <cuda_runtime.h>
#include <cuda_bf16.h>
#include <cstdint>

#define BSZ 64
#define NC  32

// Spatial sizes: 255 -> 127 -> 63 -> 31 -> 15 -> 7 (stride 2, VALID, k=3)
static const int H0 = 255, H1 = 127, H2 = 63, H3 = 31, H4 = 15, H5 = 7;

// ---------------- scratch ----------------
__device__ float g_bufA[BSZ * NC * 127 * 127];
__device__ float g_bufB[BSZ * NC * 63 * 63];
__device__ float g_feat[BSZ * NC * 7 * 7];
__device__ float g_fc1[BSZ * 20];
__device__ float g_coef[BSZ * 27];

__device__ __forceinline__ uint32_t f2tf32(float f) {
    uint32_t r;
    asm("cvt.rna.tf32.f32 %0, %1;" : "=r"(r) : "f"(f));
    return r;
}

__device__ __forceinline__ void mma_tf32(float& c0, float& c1, float& c2, float& c3,
                                         uint32_t a0, uint32_t a1, uint32_t a2, uint32_t a3,
                                         uint32_t b0, uint32_t b1) {
    asm volatile(
        "mma.sync.aligned.m16n8k8.row.col.f32.tf32.tf32.f32 "
        "{%0,%1,%2,%3}, {%4,%5,%6,%7}, {%8,%9}, {%0,%1,%2,%3};"
        : "+f"(c0), "+f"(c1), "+f"(c2), "+f"(c3)
        : "r"(a0), "r"(a1), "r"(a2), "r"(a3), "r"(b0), "r"(b1));
}

// ============ implicit-GEMM conv via tensor cores (tf32) ============
// D[oc=32][pixel] = sum_k W[oc][k] * X[k][pixel],  k = ic*9 + ky*3 + kx
// Block: 128 threads = 4 warps. Warp handles 32 consecutive linear output
// pixels (4 n-tiles of 8); M=32 as 2 m-tiles of 16. Weights (tf32) in smem,
// X gathered from global via offset table. Fused bias+relu+bn epilogue.
template <int HIN, int HOUT, int ICN>
__global__ void __launch_bounds__(128) conv_mma_kernel(
    const float* __restrict__ x, const float* __restrict__ w,
    const float* __restrict__ cbias,
    const float* __restrict__ bng, const float* __restrict__ bnb,
    const float* __restrict__ bnm, const float* __restrict__ bnv,
    float* __restrict__ out)
{
    constexpr int KREAL = ICN * 9;
    constexpr int NKS   = (KREAL + 7) / 8;     // K-steps of 8
    constexpr int KPAD  = NKS * 8;
    constexpr int SP    = KPAD + 4;            // smem row stride (bank-friendly: SP%32==4)
    constexpr int TOTAL = BSZ * HOUT * HOUT;
    constexpr int HH    = HOUT * HOUT;

    __shared__ uint32_t ws[NC * SP];
    __shared__ int   offs[KPAD];
    __shared__ float sc_s[NC], sh_s[NC], bias_s[NC];

    const int tid = threadIdx.x;
    // stage weights (tf32-converted), zero-pad k >= KREAL
    for (int i = tid; i < NC * KPAD; i += 128) {
        int oc = i / KPAD, kk = i % KPAD;
        float v = (kk < KREAL) ? w[oc * KREAL + kk] : 0.f;
        ws[oc * SP + kk] = f2tf32(v);
    }
    for (int i = tid; i < KPAD; i += 128) {
        int kk = i;
        int ic = 0, ky = 0, kx = 0;
        if (kk < KREAL) { ic = kk / 9; int r = kk % 9; ky = r / 3; kx = r % 3; }
        offs[i] = ic * HIN * HIN + ky * HIN + kx;
    }
    if (tid < NC) {
        float sc = bng[tid] * rsqrtf(bnv[tid] + 1e-5f);
        sc_s[tid]   = sc;
        sh_s[tid]   = bnb[tid] - bnm[tid] * sc;
        bias_s[tid] = cbias[tid];
    }
    __syncthreads();

    const int warp = tid >> 5;
    const int lane = tid & 31;
    const int g    = lane >> 2;        // group id (row within fragment)
    const int k0   = lane & 3;
    const int Pw   = (blockIdx.x * 4 + warp) * 32;   // warp's first pixel

    // B-gather base addresses (4 n-tiles; column n = g)
    int baseB[4];
#pragma unroll
    for (int t = 0; t < 4; ++t) {
        int p = Pw + t * 8 + g;
        int pc = p < TOTAL ? p : TOTAL - 1;
        int b  = pc / HH;
        int r  = pc - b * HH;
        int oy = r / HOUT;
        int ox = r - oy * HOUT;
        baseB[t] = ((b * ICN) * HIN + 2 * oy) * HIN + 2 * ox;
    }

    float acc[2][4][4];
#pragma unroll
    for (int mt = 0; mt < 2; ++mt)
#pragma unroll
        for (int t = 0; t < 4; ++t)
#pragma unroll
            for (int i = 0; i < 4; ++i) acc[mt][t][i] = 0.f;

    for (int ks = 0; ks < NKS; ++ks) {
        int kb = ks * 8 + k0;
        int o0 = offs[kb], o4 = offs[kb + 4];

        uint32_t a[2][4];
#pragma unroll
        for (int mt = 0; mt < 2; ++mt) {
            int m = mt * 16 + g;
            a[mt][0] = ws[m * SP + kb];
            a[mt][1] = ws[(m + 8) * SP + kb];
            a[mt][2] = ws[m * SP + kb + 4];
            a[mt][3] = ws[(m + 8) * SP + kb + 4];
        }

        uint32_t bfr[4][2];
#pragma unroll
        for (int t = 0; t < 4; ++t) {
            bfr[t][0] = f2tf32(__ldg(x + baseB[t] + o0));
            bfr[t][1] = f2tf32(__ldg(x + baseB[t] + o4));
        }

#pragma unroll
        for (int mt = 0; mt < 2; ++mt)
#pragma unroll
            for (int t = 0; t < 4; ++t)
                mma_tf32(acc[mt][t][0], acc[mt][t][1], acc[mt][t][2], acc[mt][t][3],
                         a[mt][0], a[mt][1], a[mt][2], a[mt][3],
                         bfr[t][0], bfr[t][1]);
    }

    // epilogue: thread owns columns (lane%4)*2 + {0,1} of each n-tile
#pragma unroll
    for (int t = 0; t < 4; ++t) {
#pragma unroll
        for (int j = 0; j < 2; ++j) {
            int p = Pw + t * 8 + k0 * 2 + j;
            if (p >= TOTAL) continue;
            int b  = p / HH;
            int r  = p - b * HH;
            size_t sb = (size_t)b * NC * HH + r;   // + oc*HH per row
#pragma unroll
            for (int mt = 0; mt < 2; ++mt) {
                int oc_lo = mt * 16 + g;
                int oc_hi = oc_lo + 8;
                float vlo = acc[mt][t][0 + j];
                float vhi = acc[mt][t][2 + j];
                float ylo = fmaxf(vlo + bias_s[oc_lo], 0.f) * sc_s[oc_lo] + sh_s[oc_lo];
                float yhi = fmaxf(vhi + bias_s[oc_hi], 0.f) * sc_s[oc_hi] + sh_s[oc_hi];
                out[sb + (size_t)oc_lo * HH] = ylo;
                out[sb + (size_t)oc_hi * HH] = yhi;
            }
        }
    }
}

// ---------------- FC1: [64,1568] @ [1568,20]^T + b, relu ----------------
__global__ void fc1_kernel(const float* __restrict__ feat, const float* __restrict__ w,
                           const float* __restrict__ bias, float* __restrict__ out)
{
    int gw   = (blockIdx.x * blockDim.x + threadIdx.x) >> 5;
    int lane = threadIdx.x & 31;
    if (gw >= BSZ * 20) return;
    int j = gw % 20, b = gw / 20;
    const float* f  = feat + b * 1568;
    const float* wr = w + j * 1568;
    float s = 0.f;
    for (int k = lane; k < 1568; k += 32) s = fmaf(f[k], wr[k], s);
#pragma unroll
    for (int o = 16; o; o >>= 1) s += __shfl_xor_sync(0xffffffffu, s, o);
    if (lane == 0) out[b * 20 + j] = fmaxf(s + bias[j], 0.f);
}

// ---------------- FC2 + cubic-spline solve (Thomas) ----------------
__global__ void spline_kernel(const float* __restrict__ fc1,
                              const float* __restrict__ l2w, const float* __restrict__ l2b,
                              float* __restrict__ coef)
{
    int b = blockIdx.x * blockDim.x + threadIdx.x;
    if (b >= BSZ) return;

    float ys[10];
#pragma unroll
    for (int k = 0; k < 10; ++k) {
        float s = l2b[k];
#pragma unroll
        for (int j = 0; j < 20; ++j) s = fmaf(fc1[b * 20 + j], l2w[k * 20 + j], s);
        ys[k] = s;
    }

    const float h = (float)(1.0 / 9.0);
    const float c6h2 = 6.0f * 81.0f;
    float d[8];
#pragma unroll
    for (int i = 0; i < 8; ++i) d[i] = c6h2 * (ys[i] - 2.f * ys[i + 1] + ys[i + 2]);

    float cp[8], dp[8];
    cp[0] = 0.25f; dp[0] = d[0] * 0.25f;
#pragma unroll
    for (int i = 1; i < 8; ++i) {
        float mden = 4.f - cp[i - 1];
        cp[i] = 1.f / mden;
        dp[i] = (d[i] - dp[i - 1]) / mden;
    }
    float M[10];
    M[0] = 0.f; M[9] = 0.f;
    M[8] = dp[7];
#pragma unroll
    for (int i = 6; i >= 0; --i) M[i + 1] = dp[i] - cp[i] * M[i + 2];

#pragma unroll
    for (int i = 0; i < 9; ++i) {
        coef[b * 27 + i]      = (M[i + 1] - M[i]) / (6.f * h);
        coef[b * 27 + 9 + i]  = M[i] * 0.5f;
        coef[b * 27 + 18 + i] = (ys[i + 1] - ys[i]) / h - (M[i + 1] + 2.f * M[i]) * (h / 6.f);
    }
}

// ---------------- final fused bucketize + gather + cubic eval (float4) ----------------
__global__ void eval_kernel(const float4* __restrict__ x, const float* __restrict__ coef,
                            float4* __restrict__ out, int n4)
{
    int idx = blockIdx.x * blockDim.x + threadIdx.x;
    if (idx >= n4) return;
    const int per = 3 * 255 * 255;
    int i0 = idx * 4;
    int b0 = i0 / per;
    int r0 = i0 - b0 * per;

    float4 xv = x[idx];
    float vals[4] = {xv.x, xv.y, xv.z, xv.w};
    float res[4];
    const float h = (float)(1.0 / 9.0);
#pragma unroll
    for (int j = 0; j < 4; ++j) {
        int b = b0 + ((r0 + j) >= per ? 1 : 0);
        float v = vals[j];
        float q = fminf(fmaxf(v / h, 0.f), 8.f);
        int xi = (int)floorf(q);
        float xf = v - (float)xi * h;
        const float* cf = coef + b * 27;
        float a  = __ldg(cf + xi);
        float bb = __ldg(cf + 9 + xi);
        float cc = __ldg(cf + 18 + xi);
        res[j] = ((a * xf + bb) * xf + cc) * xf;
    }
    out[idx] = make_float4(res[0], res[1], res[2], res[3]);
}

// ---------------- launch ----------------
extern "C" void kernel_launch(void* const* d_in, const int* in_sizes, int n_in,
                              void* d_out, int out_size)
{
    const float* batch = (const float*)d_in[0];
    const float* c1_w  = (const float*)d_in[1];
    const float* c1_b  = (const float*)d_in[2];
    const float* cw    = (const float*)d_in[3];
    const float* cb    = (const float*)d_in[4];
    const float* bn_g  = (const float*)d_in[5];
    const float* bn_b  = (const float*)d_in[6];
    const float* bn_m  = (const float*)d_in[7];
    const float* bn_v  = (const float*)d_in[8];
    const float* l1_w  = (const float*)d_in[9];
    const float* l1_b  = (const float*)d_in[10];
    const float* l2_w  = (const float*)d_in[11];
    const float* l2_b  = (const float*)d_in[12];
    float* out = (float*)d_out;

    float* bufA; cudaGetSymbolAddress((void**)&bufA, g_bufA);
    float* bufB; cudaGetSymbolAddress((void**)&bufB, g_bufB);
    float* feat; cudaGetSymbolAddress((void**)&feat, g_feat);
    float* fc1;  cudaGetSymbolAddress((void**)&fc1,  g_fc1);
    float* coef; cudaGetSymbolAddress((void**)&coef, g_coef);

    // conv1: 3 -> 32, 255 -> 127
    {
        int total = BSZ * H1 * H1;
        int blocks = (total + 127) / 128;
        conv_mma_kernel<H0, H1, 3><<<blocks, 128>>>(
            batch, c1_w, c1_b, bn_g, bn_b, bn_m, bn_v, bufA);
    }
    // conv2: 127 -> 63
    {
        int total = BSZ * H2 * H2;
        int blocks = (total + 127) / 128;
        conv_mma_kernel<H1, H2, NC><<<blocks, 128>>>(
            bufA, cw + 0 * NC * NC * 9, cb + 0 * NC,
            bn_g + 1 * NC, bn_b + 1 * NC, bn_m + 1 * NC, bn_v + 1 * NC, bufB);
    }
    // conv3: 63 -> 31
    {
        int total = BSZ * H3 * H3;
        int blocks = (total + 127) / 128;
        conv_mma_kernel<H2, H3, NC><<<blocks, 128>>>(
            bufB, cw + 1 * NC * NC * 9, cb + 1 * NC,
            bn_g + 2 * NC, bn_b + 2 * NC, bn_m + 2 * NC, bn_v + 2 * NC, bufA);
    }
    // conv4: 31 -> 15
    {
        int total = BSZ * H4 * H4;
        int blocks = (total + 127) / 128;
        conv_mma_kernel<H3, H4, NC><<<blocks, 128>>>(
            bufA, cw + 2 * NC * NC * 9, cb + 2 * NC,
            bn_g + 3 * NC, bn_b + 3 * NC, bn_m + 3 * NC, bn_v + 3 * NC, bufB);
    }
    // conv5: 15 -> 7
    {
        int total = BSZ * H5 * H5;
        int blocks = (total + 127) / 128;
        conv_mma_kernel<H4, H5, NC><<<blocks, 128>>>(
            bufB, cw + 3 * NC * NC * 9, cb + 3 * NC,
            bn_g + 4 * NC, bn_b + 4 * NC, bn_m + 4 * NC, bn_v + 4 * NC, feat);
    }
    // FC1
    {
        int warps = BSZ * 20;
        int threads = warps * 32;
        fc1_kernel<<<(threads + 255) / 256, 256>>>(feat, l1_w, l1_b, fc1);
    }
    // FC2 + spline solve
    spline_kernel<<<1, BSZ>>>(fc1, l2_w, l2_b, coef);

    // Final fused eval
    {
        int n4 = out_size / 4;
        eval_kernel<<<(n4 + 255) / 256, 256>>>((const float4*)batch, coef, (float4*)out, n4);
    }
}